// round 5
// baseline (speedup 1.0000x reference)
#include <cuda_runtime.h>
#include <cstdint>

// Problem dims
// B=4, S=2048, PAST=2048, L=PAST+S=4096, D=2048, DFF=8192
#define BM 128
#define BN 128
#define BK 32

// Scratch (device globals; no allocation allowed)
static __device__ float g_q[16777216];       // [4,2048,2048]
static __device__ float g_scores[33554432];  // [4,2048,4096]
static __device__ float g_ctx[16777216];     // [4,2048,2048]
static __device__ float g_ff[67108864];      // [8192,8192]

__device__ __forceinline__ unsigned f2tf(float f) {
  unsigned u;
  asm("cvt.rna.tf32.f32 %0, %1;" : "=r"(u) : "f"(f));
  return u;
}

__device__ __forceinline__ void mma8(float* c, const unsigned* a, const unsigned* b) {
  asm volatile(
      "mma.sync.aligned.m16n8k8.row.col.f32.tf32.tf32.f32 "
      "{%0,%1,%2,%3}, {%4,%5,%6,%7}, {%8,%9}, {%0,%1,%2,%3};\n"
      : "+f"(c[0]), "+f"(c[1]), "+f"(c[2]), "+f"(c[3])
      : "r"(a[0]), "r"(a[1]), "r"(a[2]), "r"(a[3]), "r"(b[0]), "r"(b[1]));
}

// C[M,N] = A[M,K] * op(B) + bias;  op(B) = B[K,N] (NN) or B[N,K]^T (NT)
// Batched via blockIdx.z with strides sAz/sBz/sCz.
// Output row remap: global row r -> C + (r/row_div)*row_stride + (r%row_div)*N
// (used to scatter k_new/v_new into the [B, PAST+S, D] cache layout).
// SPLIT = 3xTF32 hi/lo decomposition (near-fp32 accuracy): used EVERYWHERE now,
// since single-pass tf32 (~2.6e-3) fails the 1e-3 threshold.
template <bool TRANSB, bool SPLIT>
__global__ void __launch_bounds__(256) gemm_tf32(
    const float* __restrict__ A, const float* __restrict__ B,
    const float* __restrict__ bias, float* __restrict__ C,
    int M, int N, int K,
    long long sAz, long long sBz, long long sCz,
    int row_div, long long row_stride) {
  constexpr int ALD = 36;                 // [m][k] stride: banks 4q+r, conflict-free
  constexpr int BR = TRANSB ? BN : BK;
  constexpr int BLD = TRANSB ? 36 : 136;  // NN [k][n] stride 136: banks 8r+q

  extern __shared__ float smem[];
  float (*As)[BM][ALD] = (float (*)[BM][ALD])smem;
  float (*Bs)[BR][BLD] = (float (*)[BR][BLD])(smem + 2 * BM * ALD);

  const int tid = threadIdx.x;
  const int lane = tid & 31;
  const int wid = tid >> 5;
  const int wm0 = (wid >> 2) * 64;  // 2x4 warp grid, 64x32 warp tile
  const int wn0 = (wid & 3) * 32;
  const int qq = lane >> 2;
  const int rr = lane & 3;
  const int m0 = blockIdx.y * BM;
  const int n0 = blockIdx.x * BN;

  A += (long long)blockIdx.z * sAz;
  B += (long long)blockIdx.z * sBz;
  C += (long long)blockIdx.z * sCz;

  const long long ldb = TRANSB ? (long long)K : (long long)N;

  const int arow = tid >> 3;        // K-contiguous loads (A, B-NT)
  const int akc = (tid & 7) * 4;
  const int bkr = tid >> 5;         // B-NN loads
  const int bnc = (tid & 31) * 4;

  float4 ar[4], br[4];
  float acc[4][4][4];
#pragma unroll
  for (int i = 0; i < 4; i++)
#pragma unroll
    for (int j = 0; j < 4; j++)
#pragma unroll
      for (int l = 0; l < 4; l++) acc[i][j][l] = 0.f;

  auto loadA = [&](int kt) {
#pragma unroll
    for (int i = 0; i < 4; i++)
      ar[i] = *(const float4*)(A + (long long)(m0 + arow + i * 32) * K + kt + akc);
  };
  auto loadB = [&](int kt) {
#pragma unroll
    for (int i = 0; i < 4; i++) {
      if (TRANSB)
        br[i] = *(const float4*)(B + (long long)(n0 + arow + i * 32) * ldb + kt + akc);
      else
        br[i] = *(const float4*)(B + (long long)(kt + bkr + i * 8) * ldb + n0 + bnc);
    }
  };
  auto cvt4 = [&](float4 v) -> float4 {
    if (!SPLIT) {  // pre-convert to tf32 at smem-store time
      v.x = __uint_as_float(f2tf(v.x));
      v.y = __uint_as_float(f2tf(v.y));
      v.z = __uint_as_float(f2tf(v.z));
      v.w = __uint_as_float(f2tf(v.w));
    }
    return v;
  };
  auto stores = [&](int s) {
#pragma unroll
    for (int i = 0; i < 4; i++)
      *(float4*)&As[s][arow + i * 32][akc] = cvt4(ar[i]);
#pragma unroll
    for (int i = 0; i < 4; i++) {
      if (TRANSB)
        *(float4*)&Bs[s][arow + i * 32][akc] = cvt4(br[i]);
      else
        *(float4*)&Bs[s][bkr + i * 8][bnc] = cvt4(br[i]);
    }
  };

  loadA(0);
  loadB(0);
  stores(0);
  __syncthreads();

  int cur = 0;
  for (int kt = 0; kt < K; kt += BK) {
    const bool has_next = (kt + BK) < K;
    if (has_next) {  // prefetch next tile into registers, overlapped with MMA
      loadA(kt + BK);
      loadB(kt + BK);
    }

#pragma unroll
    for (int kk = 0; kk < BK; kk += 8) {
      unsigned ah[4][4], bh[4][2];
      unsigned al[4][4], bl[4][2];
#pragma unroll
      for (int mt = 0; mt < 4; mt++) {
        const int mr = wm0 + mt * 16 + qq;
        float f0 = As[cur][mr][kk + rr];
        float f1 = As[cur][mr + 8][kk + rr];
        float f2 = As[cur][mr][kk + rr + 4];
        float f3 = As[cur][mr + 8][kk + rr + 4];
        if (SPLIT) {  // 3xTF32 hi/lo split (near-fp32 accuracy)
          ah[mt][0] = f2tf(f0); al[mt][0] = f2tf(f0 - __uint_as_float(ah[mt][0]));
          ah[mt][1] = f2tf(f1); al[mt][1] = f2tf(f1 - __uint_as_float(ah[mt][1]));
          ah[mt][2] = f2tf(f2); al[mt][2] = f2tf(f2 - __uint_as_float(ah[mt][2]));
          ah[mt][3] = f2tf(f3); al[mt][3] = f2tf(f3 - __uint_as_float(ah[mt][3]));
        } else {
          ah[mt][0] = __float_as_uint(f0);
          ah[mt][1] = __float_as_uint(f1);
          ah[mt][2] = __float_as_uint(f2);
          ah[mt][3] = __float_as_uint(f3);
        }
      }
#pragma unroll
      for (int nt = 0; nt < 4; nt++) {
        const int nc = wn0 + nt * 8 + qq;
        float g0, g1;
        if (TRANSB) {
          g0 = Bs[cur][nc][kk + rr];
          g1 = Bs[cur][nc][kk + rr + 4];
        } else {
          g0 = Bs[cur][kk + rr][nc];
          g1 = Bs[cur][kk + rr + 4][nc];
        }
        if (SPLIT) {
          bh[nt][0] = f2tf(g0); bl[nt][0] = f2tf(g0 - __uint_as_float(bh[nt][0]));
          bh[nt][1] = f2tf(g1); bl[nt][1] = f2tf(g1 - __uint_as_float(bh[nt][1]));
        } else {
          bh[nt][0] = __float_as_uint(g0);
          bh[nt][1] = __float_as_uint(g1);
        }
      }
#pragma unroll
      for (int mt = 0; mt < 4; mt++)
#pragma unroll
        for (int nt = 0; nt < 4; nt++) {
          mma8(acc[mt][nt], ah[mt], bh[nt]);
          if (SPLIT) {
            mma8(acc[mt][nt], al[mt], bh[nt]);
            mma8(acc[mt][nt], ah[mt], bl[nt]);
          }
        }
    }

    if (has_next) {
      stores(cur ^ 1);
      __syncthreads();
      cur ^= 1;
    }
  }

  // epilogue (all rows of this CTA share one row_div block: BM | row_div)
  float* Cb = C + (long long)(m0 / row_div) * row_stride + (long long)(m0 % row_div) * N;
#pragma unroll
  for (int mt = 0; mt < 4; mt++) {
    const int r0 = wm0 + mt * 16 + qq;
#pragma unroll
    for (int nt = 0; nt < 4; nt++) {
      const int gc = n0 + wn0 + nt * 8 + rr * 2;
      float bv0 = 0.f, bv1 = 0.f;
      if (bias) {
        bv0 = bias[gc];
        bv1 = bias[gc + 1];
      }
      float2 v0, v1;
      v0.x = acc[mt][nt][0] + bv0;
      v0.y = acc[mt][nt][1] + bv1;
      v1.x = acc[mt][nt][2] + bv0;
      v1.y = acc[mt][nt][3] + bv1;
      *(float2*)(Cb + (long long)r0 * N + gc) = v0;
      *(float2*)(Cb + (long long)(r0 + 8) * N + gc) = v1;
    }
  }
}

// Copy [4,2048,2048] cache into rows [0,2048) of [4,4096,2048] output regions.
__global__ void copy_cache(const float* __restrict__ src, float* __restrict__ dst) {
  long long i = (long long)blockIdx.x * blockDim.x + threadIdx.x;  // float4 idx
  const long long per_b = 2048LL * 512;                            // float4 per batch
  int b = (int)(i / per_b);
  long long rem = i - (long long)b * per_b;
  const float4 v = ((const float4*)src)[i];
  ((float4*)dst)[(long long)b * 4096 * 512 + rem] = v;
}

// softmax over the QUERY axis (dim=1) of scores [4, 2048, 4096]
__global__ void softmax_q(float* __restrict__ s) {
  const int col = blockIdx.x * blockDim.x + threadIdx.x;  // key column
  float* p = s + (long long)blockIdx.y * 2048 * 4096 + col;
  float mx = -1e30f;
#pragma unroll 16
  for (int i = 0; i < 2048; i++) mx = fmaxf(mx, p[(long long)i * 4096]);
  float sum = 0.f;
#pragma unroll 16
  for (int i = 0; i < 2048; i++) sum += __expf(p[(long long)i * 4096] - mx);
  const float inv = 1.f / sum;
#pragma unroll 16
  for (int i = 0; i < 2048; i++) {
    const long long o = (long long)i * 4096;
    p[o] = __expf(p[o] - mx) * inv;
  }
}

extern "C" void kernel_launch(void* const* d_in, const int* in_sizes, int n_in,
                              void* d_out, int out_size) {
  const float* x = (const float*)d_in[0];
  const float* k_cache = (const float*)d_in[1];
  const float* v_cache = (const float*)d_in[2];
  const float* Wq = (const float*)d_in[3];
  const float* bq = (const float*)d_in[4];
  const float* Wk = (const float*)d_in[5];
  const float* bk = (const float*)d_in[6];
  const float* Wv = (const float*)d_in[7];
  const float* bv = (const float*)d_in[8];
  const float* Wff = (const float*)d_in[9];
  const float* bff = (const float*)d_in[10];
  const float* Wout = (const float*)d_in[11];
  const float* bout = (const float*)d_in[12];

  float* out = (float*)d_out;                       // [4,2048,2048]
  float* k_out = out + 16777216LL;                  // [4,4096,2048]
  float* v_out = k_out + 33554432LL;                // [4,4096,2048]

  float *qb, *sc, *cx, *ff;
  cudaGetSymbolAddress((void**)&qb, g_q);
  cudaGetSymbolAddress((void**)&sc, g_scores);
  cudaGetSymbolAddress((void**)&cx, g_ctx);
  cudaGetSymbolAddress((void**)&ff, g_ff);

  const int SMEM_NN = (2 * 128 * 36 + 2 * 32 * 136) * 4;   // 71680
  const int SMEM_NT = (2 * 128 * 36 + 2 * 128 * 36) * 4;   // 73728
  cudaFuncSetAttribute(gemm_tf32<false, true>,
                       cudaFuncAttributeMaxDynamicSharedMemorySize, SMEM_NN);
  cudaFuncSetAttribute(gemm_tf32<true, true>,
                       cudaFuncAttributeMaxDynamicSharedMemorySize, SMEM_NT);

  const dim3 blk(256);

  // KV cache copy into d_out cache regions
  copy_cache<<<16384, 256>>>(k_cache, k_out);
  copy_cache<<<16384, 256>>>(v_cache, v_out);

  // Projections: M=8192, N=2048, K=2048  (3xTF32 split — k/v are direct outputs)
  gemm_tf32<false, true><<<dim3(16, 64, 1), blk, SMEM_NN>>>(
      x, Wq, bq, qb, 8192, 2048, 2048, 0, 0, 0, 8192, 0);
  // k_new / v_new scattered into rows [2048,4096) of each batch's cache slot
  gemm_tf32<false, true><<<dim3(16, 64, 1), blk, SMEM_NN>>>(
      x, Wk, bk, k_out + 2048LL * 2048, 8192, 2048, 2048, 0, 0, 0,
      2048, 4096LL * 2048);
  gemm_tf32<false, true><<<dim3(16, 64, 1), blk, SMEM_NN>>>(
      x, Wv, bv, v_out + 2048LL * 2048, 8192, 2048, 2048, 0, 0, 0,
      2048, 4096LL * 2048);

  // scores = q @ k^T  (3xTF32 split for softmax-safe precision)
  gemm_tf32<true, true><<<dim3(32, 16, 4), blk, SMEM_NT>>>(
      qb, k_out, nullptr, sc, 2048, 4096, 2048,
      2048LL * 2048, 4096LL * 2048, 2048LL * 4096, 2048, 0);

  softmax_q<<<dim3(16, 4), 256>>>(sc);

  // ctx = attn @ v
  gemm_tf32<false, true><<<dim3(16, 16, 4), blk, SMEM_NN>>>(
      sc, v_out, nullptr, cx, 2048, 2048, 4096,
      2048LL * 4096, 4096LL * 2048, 2048LL * 2048, 2048, 0);

  // FFN
  gemm_tf32<false, true><<<dim3(64, 64, 1), blk, SMEM_NN>>>(
      cx, Wff, bff, ff, 8192, 8192, 2048, 0, 0, 0, 8192, 0);
  gemm_tf32<false, true><<<dim3(16, 64, 1), blk, SMEM_NN>>>(
      ff, Wout, bout, out, 8192, 2048, 8192, 0, 0, 0, 8192, 0);
}

// round 7
// speedup vs baseline: 1.4739x; 1.4739x over previous
#include <cuda_runtime.h>
#include <cuda_bf16.h>
#include <cstdint>

// Problem dims
// B=4, S=2048, PAST=2048, L=PAST+S=4096, D=2048, DFF=8192
#define BM 128
#define BN 128
#define BK 32

// Scratch (device globals; no allocation allowed)
static __device__ float g_q[16777216];       // [4,2048,2048]
static __device__ float g_scores[33554432];  // [4,2048,4096]
static __device__ float g_ctx[16777216];     // [4,2048,2048]
static __device__ float g_ff[67108864];      // [8192,8192]

__device__ __forceinline__ unsigned f2tf(float f) {
  unsigned u;
  asm("cvt.rna.tf32.f32 %0, %1;" : "=r"(u) : "f"(f));
  return u;
}

__device__ __forceinline__ void mma8(float* c, const unsigned* a, const unsigned* b) {
  asm volatile(
      "mma.sync.aligned.m16n8k8.row.col.f32.tf32.tf32.f32 "
      "{%0,%1,%2,%3}, {%4,%5,%6,%7}, {%8,%9}, {%0,%1,%2,%3};\n"
      : "+f"(c[0]), "+f"(c[1]), "+f"(c[2]), "+f"(c[3])
      : "r"(a[0]), "r"(a[1]), "r"(a[2]), "r"(a[3]), "r"(b[0]), "r"(b[1]));
}

__device__ __forceinline__ void mma16(float* c, const unsigned* a, const unsigned* b) {
  asm volatile(
      "mma.sync.aligned.m16n8k16.row.col.f32.bf16.bf16.f32 "
      "{%0,%1,%2,%3}, {%4,%5,%6,%7}, {%8,%9}, {%0,%1,%2,%3};\n"
      : "+f"(c[0]), "+f"(c[1]), "+f"(c[2]), "+f"(c[3])
      : "r"(a[0]), "r"(a[1]), "r"(a[2]), "r"(a[3]), "r"(b[0]), "r"(b[1]));
}

// split two floats into packed bf16 hi/lo pairs (x -> low half, y -> high half)
__device__ __forceinline__ void split2(float x, float y, unsigned& hi, unsigned& lo) {
  __nv_bfloat162 h = __floats2bfloat162_rn(x, y);
  float hx = __bfloat162float(h.x), hy = __bfloat162float(h.y);
  __nv_bfloat162 l = __floats2bfloat162_rn(x - hx, y - hy);
  hi = *(unsigned*)&h;
  lo = *(unsigned*)&l;
}

// ============================ tf32 3x-split GEMM ============================
// Used where precision matters through the softmax (q-proj, k-proj, scores).
template <bool TRANSB, bool SPLIT>
__global__ void __launch_bounds__(256) gemm_tf32(
    const float* __restrict__ A, const float* __restrict__ B,
    const float* __restrict__ bias, float* __restrict__ C,
    int M, int N, int K,
    long long sAz, long long sBz, long long sCz,
    int row_div, long long row_stride) {
  constexpr int ALD = 36;
  constexpr int BR = TRANSB ? BN : BK;
  constexpr int BLD = TRANSB ? 36 : 136;

  extern __shared__ float smem[];
  float (*As)[BM][ALD] = (float (*)[BM][ALD])smem;
  float (*Bs)[BR][BLD] = (float (*)[BR][BLD])(smem + 2 * BM * ALD);

  const int tid = threadIdx.x;
  const int lane = tid & 31;
  const int wid = tid >> 5;
  const int wm0 = (wid >> 2) * 64;
  const int wn0 = (wid & 3) * 32;
  const int qq = lane >> 2;
  const int rr = lane & 3;
  const int m0 = blockIdx.y * BM;
  const int n0 = blockIdx.x * BN;

  A += (long long)blockIdx.z * sAz;
  B += (long long)blockIdx.z * sBz;
  C += (long long)blockIdx.z * sCz;

  const long long ldb = TRANSB ? (long long)K : (long long)N;

  const int arow = tid >> 3;
  const int akc = (tid & 7) * 4;
  const int bkr = tid >> 5;
  const int bnc = (tid & 31) * 4;

  float4 ar[4], br[4];
  float acc[4][4][4];
#pragma unroll
  for (int i = 0; i < 4; i++)
#pragma unroll
    for (int j = 0; j < 4; j++)
#pragma unroll
      for (int l = 0; l < 4; l++) acc[i][j][l] = 0.f;

  auto loadA = [&](int kt) {
#pragma unroll
    for (int i = 0; i < 4; i++)
      ar[i] = *(const float4*)(A + (long long)(m0 + arow + i * 32) * K + kt + akc);
  };
  auto loadB = [&](int kt) {
#pragma unroll
    for (int i = 0; i < 4; i++) {
      if (TRANSB)
        br[i] = *(const float4*)(B + (long long)(n0 + arow + i * 32) * ldb + kt + akc);
      else
        br[i] = *(const float4*)(B + (long long)(kt + bkr + i * 8) * ldb + n0 + bnc);
    }
  };
  auto stores = [&](int s) {
#pragma unroll
    for (int i = 0; i < 4; i++)
      *(float4*)&As[s][arow + i * 32][akc] = ar[i];
#pragma unroll
    for (int i = 0; i < 4; i++) {
      if (TRANSB)
        *(float4*)&Bs[s][arow + i * 32][akc] = br[i];
      else
        *(float4*)&Bs[s][bkr + i * 8][bnc] = br[i];
    }
  };

  loadA(0);
  loadB(0);
  stores(0);
  __syncthreads();

  int cur = 0;
  for (int kt = 0; kt < K; kt += BK) {
    const bool has_next = (kt + BK) < K;
    if (has_next) {
      loadA(kt + BK);
      loadB(kt + BK);
    }

#pragma unroll
    for (int kk = 0; kk < BK; kk += 8) {
      unsigned ah[4][4], bh[4][2];
      unsigned al[4][4], bl[4][2];
#pragma unroll
      for (int mt = 0; mt < 4; mt++) {
        const int mr = wm0 + mt * 16 + qq;
        float f0 = As[cur][mr][kk + rr];
        float f1 = As[cur][mr + 8][kk + rr];
        float f2 = As[cur][mr][kk + rr + 4];
        float f3 = As[cur][mr + 8][kk + rr + 4];
        ah[mt][0] = f2tf(f0); al[mt][0] = f2tf(f0 - __uint_as_float(ah[mt][0]));
        ah[mt][1] = f2tf(f1); al[mt][1] = f2tf(f1 - __uint_as_float(ah[mt][1]));
        ah[mt][2] = f2tf(f2); al[mt][2] = f2tf(f2 - __uint_as_float(ah[mt][2]));
        ah[mt][3] = f2tf(f3); al[mt][3] = f2tf(f3 - __uint_as_float(ah[mt][3]));
      }
#pragma unroll
      for (int nt = 0; nt < 4; nt++) {
        const int nc = wn0 + nt * 8 + qq;
        float g0, g1;
        if (TRANSB) {
          g0 = Bs[cur][nc][kk + rr];
          g1 = Bs[cur][nc][kk + rr + 4];
        } else {
          g0 = Bs[cur][kk + rr][nc];
          g1 = Bs[cur][kk + rr + 4][nc];
        }
        bh[nt][0] = f2tf(g0); bl[nt][0] = f2tf(g0 - __uint_as_float(bh[nt][0]));
        bh[nt][1] = f2tf(g1); bl[nt][1] = f2tf(g1 - __uint_as_float(bh[nt][1]));
      }
#pragma unroll
      for (int mt = 0; mt < 4; mt++)
#pragma unroll
        for (int nt = 0; nt < 4; nt++) {
          mma8(acc[mt][nt], ah[mt], bh[nt]);
          mma8(acc[mt][nt], al[mt], bh[nt]);
          mma8(acc[mt][nt], ah[mt], bl[nt]);
        }
    }

    if (has_next) {
      stores(cur ^ 1);
      __syncthreads();
      cur ^= 1;
    }
  }

  float* Cb = C + (long long)(m0 / row_div) * row_stride + (long long)(m0 % row_div) * N;
#pragma unroll
  for (int mt = 0; mt < 4; mt++) {
    const int r0 = wm0 + mt * 16 + qq;
#pragma unroll
    for (int nt = 0; nt < 4; nt++) {
      const int gc = n0 + wn0 + nt * 8 + rr * 2;
      float bv0 = 0.f, bv1 = 0.f;
      if (bias) {
        bv0 = bias[gc];
        bv1 = bias[gc + 1];
      }
      float2 v0, v1;
      v0.x = acc[mt][nt][0] + bv0;
      v0.y = acc[mt][nt][1] + bv1;
      v1.x = acc[mt][nt][2] + bv0;
      v1.y = acc[mt][nt][3] + bv1;
      *(float2*)(Cb + (long long)r0 * N + gc) = v0;
      *(float2*)(Cb + (long long)(r0 + 8) * N + gc) = v1;
    }
  }
}

// ============================ bf16x3 NN GEMM ============================
// hi/lo bf16 split performed ONCE at smem-store time (packed bf162 along k).
// 3 MMA m16n8k16 per k16 => half the tensor instructions of 3xTF32.
// Used for v-proj, ctx=attn@V, and both FFN GEMMs (linear error ~1e-5).
__global__ void __launch_bounds__(256) gemm_bf16x3(
    const float* __restrict__ A, const float* __restrict__ B,
    const float* __restrict__ bias, float* __restrict__ C,
    int M, int N, int K,
    long long sAz, long long sBz, long long sCz,
    int row_div, long long row_stride) {
  constexpr int ALD = 20;   // bf162 per A row (16 used): frag banks 4*perm(qq)+rr
  constexpr int BLD = 136;  // bf162 per B kpair row (128 used): banks 8rr+qq

  extern __shared__ __nv_bfloat162 smb[];
  __nv_bfloat162 (*Ahi)[BM][ALD] = (__nv_bfloat162 (*)[BM][ALD])smb;
  __nv_bfloat162 (*Alo)[BM][ALD] = (__nv_bfloat162 (*)[BM][ALD])(smb + 2 * BM * ALD);
  __nv_bfloat162 (*Bhi)[16][BLD] = (__nv_bfloat162 (*)[16][BLD])(smb + 4 * BM * ALD);
  __nv_bfloat162 (*Blo)[16][BLD] =
      (__nv_bfloat162 (*)[16][BLD])(smb + 4 * BM * ALD + 2 * 16 * BLD);

  const int tid = threadIdx.x;
  const int lane = tid & 31;
  const int wid = tid >> 5;
  const int wm0 = (wid >> 2) * 64;
  const int wn0 = (wid & 3) * 32;
  const int qq = lane >> 2;
  const int rr = lane & 3;
  const int m0 = blockIdx.y * BM;
  const int n0 = blockIdx.x * BN;

  A += (long long)blockIdx.z * sAz;
  B += (long long)blockIdx.z * sBz;
  C += (long long)blockIdx.z * sCz;

  const int arow = tid >> 3;        // A: rows arow+i*32, float4 at akc
  const int akc = (tid & 7) * 4;
  const int bkp = tid >> 5;         // B: kpairs bkp, bkp+8
  const int bnc = (tid & 31) * 4;   // B: 4 consecutive n

  float4 ar[4], br0[2], br1[2];
  float acc[4][4][4];
#pragma unroll
  for (int i = 0; i < 4; i++)
#pragma unroll
    for (int j = 0; j < 4; j++)
#pragma unroll
      for (int l = 0; l < 4; l++) acc[i][j][l] = 0.f;

  auto loadA = [&](int kt) {
#pragma unroll
    for (int i = 0; i < 4; i++)
      ar[i] = *(const float4*)(A + (long long)(m0 + arow + i * 32) * K + kt + akc);
  };
  auto loadB = [&](int kt) {
#pragma unroll
    for (int i = 0; i < 2; i++) {
      const long long r0 = (long long)(kt + 2 * (bkp + i * 8)) * N + n0 + bnc;
      br0[i] = *(const float4*)(B + r0);
      br1[i] = *(const float4*)(B + r0 + N);
    }
  };
  auto stores = [&](int s) {
#pragma unroll
    for (int i = 0; i < 4; i++) {
      unsigned h0, l0, h1, l1;
      split2(ar[i].x, ar[i].y, h0, l0);
      split2(ar[i].z, ar[i].w, h1, l1);
      *(uint2*)&Ahi[s][arow + i * 32][akc >> 1] = make_uint2(h0, h1);
      *(uint2*)&Alo[s][arow + i * 32][akc >> 1] = make_uint2(l0, l1);
    }
#pragma unroll
    for (int i = 0; i < 2; i++) {
      unsigned h[4], l[4];
      split2(br0[i].x, br1[i].x, h[0], l[0]);  // low = even k, high = odd k
      split2(br0[i].y, br1[i].y, h[1], l[1]);
      split2(br0[i].z, br1[i].z, h[2], l[2]);
      split2(br0[i].w, br1[i].w, h[3], l[3]);
      *(uint4*)&Bhi[s][bkp + i * 8][bnc] = make_uint4(h[0], h[1], h[2], h[3]);
      *(uint4*)&Blo[s][bkp + i * 8][bnc] = make_uint4(l[0], l[1], l[2], l[3]);
    }
  };

  loadA(0);
  loadB(0);
  stores(0);
  __syncthreads();

  int cur = 0;
  for (int kt = 0; kt < K; kt += BK) {
    const bool has_next = (kt + BK) < K;
    if (has_next) {
      loadA(kt + BK);
      loadB(kt + BK);
    }

#pragma unroll
    for (int c = 0; c < 2; c++) {  // two k16 chunks per BK=32
      const int kb = c * 8;        // kpair base
      unsigned ah[4][4], al[4][4], bh[4][2], bl[4][2];
#pragma unroll
      for (int mt = 0; mt < 4; mt++) {
        const int mr = wm0 + mt * 16 + qq;
        ah[mt][0] = *(const unsigned*)&Ahi[cur][mr][kb + rr];
        ah[mt][1] = *(const unsigned*)&Ahi[cur][mr + 8][kb + rr];
        ah[mt][2] = *(const unsigned*)&Ahi[cur][mr][kb + rr + 4];
        ah[mt][3] = *(const unsigned*)&Ahi[cur][mr + 8][kb + rr + 4];
        al[mt][0] = *(const unsigned*)&Alo[cur][mr][kb + rr];
        al[mt][1] = *(const unsigned*)&Alo[cur][mr + 8][kb + rr];
        al[mt][2] = *(const unsigned*)&Alo[cur][mr][kb + rr + 4];
        al[mt][3] = *(const unsigned*)&Alo[cur][mr + 8][kb + rr + 4];
      }
#pragma unroll
      for (int nt = 0; nt < 4; nt++) {
        const int nc = wn0 + nt * 8 + qq;
        bh[nt][0] = *(const unsigned*)&Bhi[cur][kb + rr][nc];
        bh[nt][1] = *(const unsigned*)&Bhi[cur][kb + rr + 4][nc];
        bl[nt][0] = *(const unsigned*)&Blo[cur][kb + rr][nc];
        bl[nt][1] = *(const unsigned*)&Blo[cur][kb + rr + 4][nc];
      }
#pragma unroll
      for (int mt = 0; mt < 4; mt++)
#pragma unroll
        for (int nt = 0; nt < 4; nt++) {
          mma16(acc[mt][nt], ah[mt], bh[nt]);
          mma16(acc[mt][nt], al[mt], bh[nt]);
          mma16(acc[mt][nt], ah[mt], bl[nt]);
        }
    }

    if (has_next) {
      stores(cur ^ 1);
      __syncthreads();
      cur ^= 1;
    }
  }

  float* Cb = C + (long long)(m0 / row_div) * row_stride + (long long)(m0 % row_div) * N;
#pragma unroll
  for (int mt = 0; mt < 4; mt++) {
    const int r0 = wm0 + mt * 16 + qq;
#pragma unroll
    for (int nt = 0; nt < 4; nt++) {
      const int gc = n0 + wn0 + nt * 8 + rr * 2;
      float bv0 = 0.f, bv1 = 0.f;
      if (bias) {
        bv0 = bias[gc];
        bv1 = bias[gc + 1];
      }
      float2 v0, v1;
      v0.x = acc[mt][nt][0] + bv0;
      v0.y = acc[mt][nt][1] + bv1;
      v1.x = acc[mt][nt][2] + bv0;
      v1.y = acc[mt][nt][3] + bv1;
      *(float2*)(Cb + (long long)r0 * N + gc) = v0;
      *(float2*)(Cb + (long long)(r0 + 8) * N + gc) = v1;
    }
  }
}

// Copy [4,2048,2048] cache into rows [0,2048) of [4,4096,2048] output regions.
__global__ void copy_cache(const float* __restrict__ src, float* __restrict__ dst) {
  long long i = (long long)blockIdx.x * blockDim.x + threadIdx.x;
  const long long per_b = 2048LL * 512;
  int b = (int)(i / per_b);
  long long rem = i - (long long)b * per_b;
  const float4 v = ((const float4*)src)[i];
  ((float4*)dst)[(long long)b * 4096 * 512 + rem] = v;
}

// softmax over the QUERY axis (dim=1) of scores [4, 2048, 4096]
__global__ void softmax_q(float* __restrict__ s) {
  const int col = blockIdx.x * blockDim.x + threadIdx.x;
  float* p = s + (long long)blockIdx.y * 2048 * 4096 + col;
  float mx = -1e30f;
#pragma unroll 16
  for (int i = 0; i < 2048; i++) mx = fmaxf(mx, p[(long long)i * 4096]);
  float sum = 0.f;
#pragma unroll 16
  for (int i = 0; i < 2048; i++) sum += __expf(p[(long long)i * 4096] - mx);
  const float inv = 1.f / sum;
#pragma unroll 16
  for (int i = 0; i < 2048; i++) {
    const long long o = (long long)i * 4096;
    p[o] = __expf(p[o] - mx) * inv;
  }
}

extern "C" void kernel_launch(void* const* d_in, const int* in_sizes, int n_in,
                              void* d_out, int out_size) {
  const float* x = (const float*)d_in[0];
  const float* k_cache = (const float*)d_in[1];
  const float* v_cache = (const float*)d_in[2];
  const float* Wq = (const float*)d_in[3];
  const float* bq = (const float*)d_in[4];
  const float* Wk = (const float*)d_in[5];
  const float* bk = (const float*)d_in[6];
  const float* Wv = (const float*)d_in[7];
  const float* bv = (const float*)d_in[8];
  const float* Wff = (const float*)d_in[9];
  const float* bff = (const float*)d_in[10];
  const float* Wout = (const float*)d_in[11];
  const float* bout = (const float*)d_in[12];

  float* out = (float*)d_out;                       // [4,2048,2048]
  float* k_out = out + 16777216LL;                  // [4,4096,2048]
  float* v_out = k_out + 33554432LL;                // [4,4096,2048]

  float *qb, *sc, *cx, *ff;
  cudaGetSymbolAddress((void**)&qb, g_q);
  cudaGetSymbolAddress((void**)&sc, g_scores);
  cudaGetSymbolAddress((void**)&cx, g_ctx);
  cudaGetSymbolAddress((void**)&ff, g_ff);

  const int SMEM_NN = (2 * 128 * 36 + 2 * 32 * 136) * 4;     // 71680
  const int SMEM_NT = (2 * 128 * 36 + 2 * 128 * 36) * 4;     // 73728
  const int SMEM_BF = (4 * 128 * 20 + 4 * 16 * 136) * 4;     // 75776
  cudaFuncSetAttribute(gemm_tf32<false, true>,
                       cudaFuncAttributeMaxDynamicSharedMemorySize, SMEM_NN);
  cudaFuncSetAttribute(gemm_tf32<true, true>,
                       cudaFuncAttributeMaxDynamicSharedMemorySize, SMEM_NT);
  cudaFuncSetAttribute(gemm_bf16x3,
                       cudaFuncAttributeMaxDynamicSharedMemorySize, SMEM_BF);

  const dim3 blk(256);

  // KV cache copy into d_out cache regions
  copy_cache<<<16384, 256>>>(k_cache, k_out);
  copy_cache<<<16384, 256>>>(v_cache, v_out);

  // q/k projections stay 3xTF32 (feed softmax via exp -> abs-error sensitive)
  gemm_tf32<false, true><<<dim3(16, 64, 1), blk, SMEM_NN>>>(
      x, Wq, bq, qb, 8192, 2048, 2048, 0, 0, 0, 8192, 0);
  gemm_tf32<false, true><<<dim3(16, 64, 1), blk, SMEM_NN>>>(
      x, Wk, bk, k_out + 2048LL * 2048, 8192, 2048, 2048, 0, 0, 0,
      2048, 4096LL * 2048);
  // v projection: bf16x3 (linear error path)
  gemm_bf16x3<<<dim3(16, 64, 1), blk, SMEM_BF>>>(
      x, Wv, bv, v_out + 2048LL * 2048, 8192, 2048, 2048, 0, 0, 0,
      2048, 4096LL * 2048);

  // scores = q @ k^T  (3xTF32 split for softmax-safe precision)
  gemm_tf32<true, true><<<dim3(32, 16, 4), blk, SMEM_NT>>>(
      qb, k_out, nullptr, sc, 2048, 4096, 2048,
      2048LL * 2048, 4096LL * 2048, 2048LL * 4096, 2048, 0);

  softmax_q<<<dim3(16, 4), 256>>>(sc);

  // ctx = attn @ v  (bf16x3)
  gemm_bf16x3<<<dim3(16, 16, 4), blk, SMEM_BF>>>(
      sc, v_out, nullptr, cx, 2048, 2048, 4096,
      2048LL * 4096, 4096LL * 2048, 2048LL * 2048, 2048, 0);

  // FFN (bf16x3)
  gemm_bf16x3<<<dim3(64, 64, 1), blk, SMEM_BF>>>(
      cx, Wff, bff, ff, 8192, 8192, 2048, 0, 0, 0, 8192, 0);
  gemm_bf16x3<<<dim3(16, 64, 1), blk, SMEM_BF>>>(
      ff, Wout, bout, out, 8192, 2048, 8192, 0, 0, 0, 8192, 0);
}

// round 11
// speedup vs baseline: 1.7836x; 1.2102x over previous
#include <cuda_runtime.h>
#include <cuda_fp16.h>
#include <cstdint>

// B=4, S=2048, PAST=2048, L=PAST+S=4096, D=2048, DFF=8192
#define BM 128
#define BN 128
#define BK 32

// Scratch (device globals; no allocation allowed)
static __device__ float g_q[16777216];       // [4,2048,2048]
static __device__ float g_scores[33554432];  // [4,2048,4096]
static __device__ float g_ctx[16777216];     // [4,2048,2048]
static __device__ float g_ff[67108864];      // [8192,8192]

__device__ __forceinline__ void mma16(float* c, const unsigned* a, const unsigned* b) {
  asm volatile(
      "mma.sync.aligned.m16n8k16.row.col.f32.f16.f16.f32 "
      "{%0,%1,%2,%3}, {%4,%5,%6,%7}, {%8,%9}, {%0,%1,%2,%3};\n"
      : "+f"(c[0]), "+f"(c[1]), "+f"(c[2]), "+f"(c[3])
      : "r"(a[0]), "r"(a[1]), "r"(a[2]), "r"(a[3]), "r"(b[0]), "r"(b[1]));
}

// split two floats into packed fp16 hi/lo pairs (x -> low half, y -> high half)
__device__ __forceinline__ void split2h(float x, float y, unsigned& hi, unsigned& lo) {
  __half2 h = __floats2half2_rn(x, y);
  __half2 l = __floats2half2_rn(x - __half2float(h.x), y - __half2float(h.y));
  hi = *(unsigned*)&h;
  lo = *(unsigned*)&l;
}

// ===================== fp16x3 GEMM (hi/lo split, 3 MMA per k16) =====================
// C[M,N] = A[M,K] @ op(B) + bias; op(B)=B[K,N] (NN) or B[N,K]^T (NT).
// Split done ONCE at smem-store time; per-product error ~2^-22 => near-fp32.
// Batched via blockIdx.z; k/v-cache scatter via row_div/row_stride remap.
template <bool TRANSB>
__global__ void __launch_bounds__(256) gemm_fp16x3(
    const float* __restrict__ A, const float* __restrict__ B,
    const float* __restrict__ bias, float* __restrict__ C,
    int M, int N, int K,
    long long sAz, long long sBz, long long sCz,
    int row_div, long long row_stride) {
  constexpr int ALD = 20;   // half2 words per A row (16 used): conflict-free frags
  constexpr int BLDN = 136; // NN: half2 words per kpair row (128 used)
  constexpr int BR = TRANSB ? BN : 16;
  constexpr int BLD = TRANSB ? 20 : BLDN;

  extern __shared__ unsigned smu[];
  unsigned (*Ahi)[BM][ALD] = (unsigned (*)[BM][ALD])smu;
  unsigned (*Alo)[BM][ALD] = (unsigned (*)[BM][ALD])(smu + 2 * BM * ALD);
  unsigned (*Bhi)[BR][BLD] = (unsigned (*)[BR][BLD])(smu + 4 * BM * ALD);
  unsigned (*Blo)[BR][BLD] = (unsigned (*)[BR][BLD])(smu + 4 * BM * ALD + 2 * BR * BLD);

  const int tid = threadIdx.x;
  const int lane = tid & 31;
  const int wid = tid >> 5;
  const int wm0 = (wid >> 2) * 64;  // 2x4 warp grid, 64x32 warp tiles
  const int wn0 = (wid & 3) * 32;
  const int qq = lane >> 2;
  const int rr = lane & 3;
  const int m0 = blockIdx.y * BM;
  const int n0 = blockIdx.x * BN;

  A += (long long)blockIdx.z * sAz;
  B += (long long)blockIdx.z * sBz;
  C += (long long)blockIdx.z * sCz;

  const int arow = tid >> 3;       // K-contiguous loads (A, B-NT): rows +i*32
  const int akc = (tid & 7) * 4;   // 4 consecutive k (2 kpairs)
  const int bkp = tid >> 5;        // B-NN: kpair rows bkp, bkp+8
  const int bnc = (tid & 31) * 4;  // B-NN: 4 consecutive n

  float4 ar[4], br0[4], br1[2];
  float acc[4][4][4];
#pragma unroll
  for (int i = 0; i < 4; i++)
#pragma unroll
    for (int j = 0; j < 4; j++)
#pragma unroll
      for (int l = 0; l < 4; l++) acc[i][j][l] = 0.f;

  auto loadA = [&](int kt) {
#pragma unroll
    for (int i = 0; i < 4; i++)
      ar[i] = *(const float4*)(A + (long long)(m0 + arow + i * 32) * K + kt + akc);
  };
  auto loadB = [&](int kt) {
    if (TRANSB) {
#pragma unroll
      for (int i = 0; i < 4; i++)
        br0[i] = *(const float4*)(B + (long long)(n0 + arow + i * 32) * K + kt + akc);
    } else {
#pragma unroll
      for (int i = 0; i < 2; i++) {
        const long long r0 = (long long)(kt + 2 * (bkp + i * 8)) * N + n0 + bnc;
        br0[i] = *(const float4*)(B + r0);
        br1[i] = *(const float4*)(B + r0 + N);
      }
    }
  };
  auto stores = [&](int s) {
#pragma unroll
    for (int i = 0; i < 4; i++) {  // A: pairs along k within the float4
      unsigned h0, l0, h1, l1;
      split2h(ar[i].x, ar[i].y, h0, l0);
      split2h(ar[i].z, ar[i].w, h1, l1);
      *(uint2*)&Ahi[s][arow + i * 32][akc >> 1] = make_uint2(h0, h1);
      *(uint2*)&Alo[s][arow + i * 32][akc >> 1] = make_uint2(l0, l1);
    }
    if (TRANSB) {
#pragma unroll
      for (int i = 0; i < 4; i++) {
        unsigned h0, l0, h1, l1;
        split2h(br0[i].x, br0[i].y, h0, l0);
        split2h(br0[i].z, br0[i].w, h1, l1);
        *(uint2*)&Bhi[s][arow + i * 32][akc >> 1] = make_uint2(h0, h1);
        *(uint2*)&Blo[s][arow + i * 32][akc >> 1] = make_uint2(l0, l1);
      }
    } else {
#pragma unroll
      for (int i = 0; i < 2; i++) {  // pack (even k, odd k) across two rows
        unsigned h[4], l[4];
        split2h(br0[i].x, br1[i].x, h[0], l[0]);
        split2h(br0[i].y, br1[i].y, h[1], l[1]);
        split2h(br0[i].z, br1[i].z, h[2], l[2]);
        split2h(br0[i].w, br1[i].w, h[3], l[3]);
        *(uint4*)&Bhi[s][bkp + i * 8][bnc] = make_uint4(h[0], h[1], h[2], h[3]);
        *(uint4*)&Blo[s][bkp + i * 8][bnc] = make_uint4(l[0], l[1], l[2], l[3]);
      }
    }
  };

  loadA(0);
  loadB(0);
  stores(0);
  __syncthreads();

  int cur = 0;
  for (int kt = 0; kt < K; kt += BK) {
    const bool has_next = (kt + BK) < K;
    if (has_next) {  // register prefetch overlapped with MMAs
      loadA(kt + BK);
      loadB(kt + BK);
    }

#pragma unroll
    for (int c = 0; c < 2; c++) {  // two k16 chunks per BK=32
      const int kb = c * 8;        // kpair base
      unsigned ah[4][4], al[4][4], bh[4][2], bl[4][2];
#pragma unroll
      for (int mt = 0; mt < 4; mt++) {
        const int mr = wm0 + mt * 16 + qq;
        ah[mt][0] = Ahi[cur][mr][kb + rr];
        ah[mt][1] = Ahi[cur][mr + 8][kb + rr];
        ah[mt][2] = Ahi[cur][mr][kb + rr + 4];
        ah[mt][3] = Ahi[cur][mr + 8][kb + rr + 4];
        al[mt][0] = Alo[cur][mr][kb + rr];
        al[mt][1] = Alo[cur][mr + 8][kb + rr];
        al[mt][2] = Alo[cur][mr][kb + rr + 4];
        al[mt][3] = Alo[cur][mr + 8][kb + rr + 4];
      }
#pragma unroll
      for (int nt = 0; nt < 4; nt++) {
        const int nc = wn0 + nt * 8 + qq;
        if (TRANSB) {
          bh[nt][0] = Bhi[cur][nc][kb + rr];
          bh[nt][1] = Bhi[cur][nc][kb + rr + 4];
          bl[nt][0] = Blo[cur][nc][kb + rr];
          bl[nt][1] = Blo[cur][nc][kb + rr + 4];
        } else {
          bh[nt][0] = Bhi[cur][kb + rr][nc];
          bh[nt][1] = Bhi[cur][kb + rr + 4][nc];
          bl[nt][0] = Blo[cur][kb + rr][nc];
          bl[nt][1] = Blo[cur][kb + rr + 4][nc];
        }
      }
#pragma unroll
      for (int mt = 0; mt < 4; mt++)
#pragma unroll
        for (int nt = 0; nt < 4; nt++) {
          mma16(acc[mt][nt], ah[mt], bh[nt]);
          mma16(acc[mt][nt], al[mt], bh[nt]);
          mma16(acc[mt][nt], ah[mt], bl[nt]);
        }
    }

    if (has_next) {
      stores(cur ^ 1);
      __syncthreads();
      cur ^= 1;
    }
  }

  // epilogue (all rows of this CTA share one row_div block: BM | row_div)
  float* Cb = C + (long long)(m0 / row_div) * row_stride + (long long)(m0 % row_div) * N;
#pragma unroll
  for (int mt = 0; mt < 4; mt++) {
    const int r0 = wm0 + mt * 16 + qq;
#pragma unroll
    for (int nt = 0; nt < 4; nt++) {
      const int gc = n0 + wn0 + nt * 8 + rr * 2;
      float bv0 = 0.f, bv1 = 0.f;
      if (bias) {
        bv0 = bias[gc];
        bv1 = bias[gc + 1];
      }
      float2 v0, v1;
      v0.x = acc[mt][nt][0] + bv0;
      v0.y = acc[mt][nt][1] + bv1;
      v1.x = acc[mt][nt][2] + bv0;
      v1.y = acc[mt][nt][3] + bv1;
      *(float2*)(Cb + (long long)r0 * N + gc) = v0;
      *(float2*)(Cb + (long long)(r0 + 8) * N + gc) = v1;
    }
  }
}

// Copy [4,2048,2048] cache into rows [0,2048) of [4,4096,2048] output regions.
__global__ void copy_cache(const float* __restrict__ src, float* __restrict__ dst) {
  long long i = (long long)blockIdx.x * blockDim.x + threadIdx.x;
  const long long per_b = 2048LL * 512;
  int b = (int)(i / per_b);
  long long rem = i - (long long)b * per_b;
  const float4 v = ((const float4*)src)[i];
  ((float4*)dst)[(long long)b * 4096 * 512 + rem] = v;
}

// softmax over the QUERY axis (dim=1) of scores [4, 2048, 4096]
__global__ void softmax_q(float* __restrict__ s) {
  const int col = blockIdx.x * blockDim.x + threadIdx.x;
  float* p = s + (long long)blockIdx.y * 2048 * 4096 + col;
  float mx = -1e30f;
#pragma unroll 16
  for (int i = 0; i < 2048; i++) mx = fmaxf(mx, p[(long long)i * 4096]);
  float sum = 0.f;
#pragma unroll 16
  for (int i = 0; i < 2048; i++) sum += __expf(p[(long long)i * 4096] - mx);
  const float inv = 1.f / sum;
#pragma unroll 16
  for (int i = 0; i < 2048; i++) {
    const long long o = (long long)i * 4096;
    p[o] = __expf(p[o] - mx) * inv;
  }
}

extern "C" void kernel_launch(void* const* d_in, const int* in_sizes, int n_in,
                              void* d_out, int out_size) {
  const float* x = (const float*)d_in[0];
  const float* k_cache = (const float*)d_in[1];
  const float* v_cache = (const float*)d_in[2];
  const float* Wq = (const float*)d_in[3];
  const float* bq = (const float*)d_in[4];
  const float* Wk = (const float*)d_in[5];
  const float* bk = (const float*)d_in[6];
  const float* Wv = (const float*)d_in[7];
  const float* bv = (const float*)d_in[8];
  const float* Wff = (const float*)d_in[9];
  const float* bff = (const float*)d_in[10];
  const float* Wout = (const float*)d_in[11];
  const float* bout = (const float*)d_in[12];

  float* out = (float*)d_out;            // [4,2048,2048]
  float* k_out = out + 16777216LL;       // [4,4096,2048]
  float* v_out = k_out + 33554432LL;     // [4,4096,2048]

  float *qb, *sc, *cx, *ff;
  cudaGetSymbolAddress((void**)&qb, g_q);
  cudaGetSymbolAddress((void**)&sc, g_scores);
  cudaGetSymbolAddress((void**)&cx, g_ctx);
  cudaGetSymbolAddress((void**)&ff, g_ff);

  const int SMEM_NN = (4 * 128 * 20 + 4 * 16 * 136) * 4;   // 75776
  const int SMEM_NT = (4 * 128 * 20 + 4 * 128 * 20) * 4;   // 81920
  cudaFuncSetAttribute(gemm_fp16x3<false>,
                       cudaFuncAttributeMaxDynamicSharedMemorySize, SMEM_NN);
  cudaFuncSetAttribute(gemm_fp16x3<true>,
                       cudaFuncAttributeMaxDynamicSharedMemorySize, SMEM_NT);

  const dim3 blk(256);

  // KV cache copy into d_out cache regions
  copy_cache<<<16384, 256>>>(k_cache, k_out);
  copy_cache<<<16384, 256>>>(v_cache, v_out);

  // Projections: M=8192, N=2048, K=2048
  gemm_fp16x3<false><<<dim3(16, 64, 1), blk, SMEM_NN>>>(
      x, Wq, bq, qb, 8192, 2048, 2048, 0, 0, 0, 8192, 0);
  gemm_fp16x3<false><<<dim3(16, 64, 1), blk, SMEM_NN>>>(
      x, Wk, bk, k_out + 2048LL * 2048, 8192, 2048, 2048, 0, 0, 0,
      2048, 4096LL * 2048);
  gemm_fp16x3<false><<<dim3(16, 64, 1), blk, SMEM_NN>>>(
      x, Wv, bv, v_out + 2048LL * 2048, 8192, 2048, 2048, 0, 0, 0,
      2048, 4096LL * 2048);

  // scores = q @ k^T  (NT: B = k rows [n][k])
  gemm_fp16x3<true><<<dim3(32, 16, 4), blk, SMEM_NT>>>(
      qb, k_out, nullptr, sc, 2048, 4096, 2048,
      2048LL * 2048, 4096LL * 2048, 2048LL * 4096, 2048, 0);

  softmax_q<<<dim3(16, 4), 256>>>(sc);

  // ctx = attn @ v  (NN: v_out is [k=4096][n=2048] per batch)
  gemm_fp16x3<false><<<dim3(16, 16, 4), blk, SMEM_NN>>>(
      sc, v_out, nullptr, cx, 2048, 2048, 4096,
      2048LL * 4096, 4096LL * 2048, 2048LL * 2048, 2048, 0);

  // FFN
  gemm_fp16x3<false><<<dim3(64, 64, 1), blk, SMEM_NN>>>(
      cx, Wff, bff, ff, 8192, 8192, 2048, 0, 0, 0, 8192, 0);
  gemm_fp16x3<false><<<dim3(16, 64, 1), blk, SMEM_NN>>>(
      ff, Wout, bout, out, 8192, 2048, 8192, 0, 0, 0, 8192, 0);
}

// round 13
// speedup vs baseline: 1.8599x; 1.0428x over previous
#include <cuda_runtime.h>
#include <cuda_fp16.h>
#include <cstdint>

// B=4, S=2048, PAST=2048, L=4096, D=2048, DFF=8192
// All GEMMs: C = A[M,K] @ B[N,K]^T (+bias), operands pre-split fp16 hi/lo.

// fp32 scratch
static __device__ float g_scores[33554432];  // [4,2048,4096] pre-softmax
// fp16 hi/lo planes
static __device__ __half g_xh[16777216], g_xl[16777216];          // x [8192,2048]
static __device__ __half g_wqh[4194304], g_wql[4194304];          // Wq^T [2048,2048]
static __device__ __half g_wkh[4194304], g_wkl[4194304];
static __device__ __half g_wvh[4194304], g_wvl[4194304];
static __device__ __half g_wfh[16777216], g_wfl[16777216];        // Wff^T [8192,2048]
static __device__ __half g_woh[16777216], g_wol[16777216];        // Wout^T [2048,8192]
static __device__ __half g_qh[16777216], g_ql[16777216];          // q [4,2048,2048]
static __device__ __half g_kh[33554432], g_kl[33554432];          // k [4,4096,2048]
static __device__ __half g_vth[33554432], g_vtl[33554432];        // V^T [4,2048,4096]
static __device__ __half g_sh[33554432], g_sl[33554432];          // attn [4,2048,4096]
static __device__ __half g_ch[16777216], g_cl[16777216];          // ctx [4,2048,2048]
static __device__ __half g_fh[67108864], g_fl[67108864];          // ff [8192,8192]

__device__ __forceinline__ uint32_t smem_u32(const void* p) {
  uint32_t a;
  asm("{ .reg .u64 t; cvta.to.shared.u64 t, %1; cvt.u32.u64 %0, t; }" : "=r"(a) : "l"(p));
  return a;
}
__device__ __forceinline__ void mma16(float* c, const unsigned* a, const unsigned* b) {
  asm volatile(
      "mma.sync.aligned.m16n8k16.row.col.f32.f16.f16.f32 "
      "{%0,%1,%2,%3}, {%4,%5,%6,%7}, {%8,%9}, {%0,%1,%2,%3};\n"
      : "+f"(c[0]), "+f"(c[1]), "+f"(c[2]), "+f"(c[3])
      : "r"(a[0]), "r"(a[1]), "r"(a[2]), "r"(a[3]), "r"(b[0]), "r"(b[1]));
}
__device__ __forceinline__ void ldsm4(unsigned* r, uint32_t a) {
  asm volatile("ldmatrix.sync.aligned.m8n8.x4.shared.b16 {%0,%1,%2,%3}, [%4];"
               : "=r"(r[0]), "=r"(r[1]), "=r"(r[2]), "=r"(r[3]) : "r"(a));
}
#define CP_ASYNC16(dst, src) \
  asm volatile("cp.async.cg.shared.global [%0], [%1], 16;" :: "r"(dst), "l"(src))
#define CP_COMMIT asm volatile("cp.async.commit_group;" ::: "memory")

__device__ __forceinline__ void split2h(float x, float y, unsigned& hi, unsigned& lo) {
  __half2 h = __floats2half2_rn(x, y);
  __half2 l = __floats2half2_rn(x - __half2float(h.x), y - __half2float(h.y));
  hi = *(unsigned*)&h;
  lo = *(unsigned*)&l;
}

// ============ fp16x3 NT GEMM: cp.async 4-stage + ldmatrix fragments ============
// smem per stage: 4 planes (Ahi,Alo,Bhi,Blo) of [128 rows][80B] = 40960B; 4 stages.
template <bool EMIT>
__global__ void __launch_bounds__(256) gemm_h(
    const __half* __restrict__ Ah, const __half* __restrict__ Al,
    const __half* __restrict__ Bh, const __half* __restrict__ Bl,
    const float* __restrict__ bias, float* __restrict__ C,
    __half* __restrict__ Ch, __half* __restrict__ Cl,
    int M, int N, int K,
    long long sAz, long long sBz, long long sCz,
    int row_div, long long row_stride) {
  constexpr int STG = 40960;
  extern __shared__ char smem[];
  const uint32_t sbase = smem_u32(smem);

  const int tid = threadIdx.x;
  const int lane = tid & 31;
  const int wid = tid >> 5;
  const int wm0 = (wid >> 2) * 64;  // 2x4 warp grid, 64x32 warp tiles
  const int wn0 = (wid & 3) * 32;
  const int m0 = blockIdx.y * 128;
  const int n0 = blockIdx.x * 128;

  Ah += (long long)blockIdx.z * sAz;
  Al += (long long)blockIdx.z * sAz;
  Bh += (long long)blockIdx.z * sBz;
  Bl += (long long)blockIdx.z * sBz;
  if (C) C += (long long)blockIdx.z * sCz;
  if (EMIT) {
    Ch += (long long)blockIdx.z * sCz;
    Cl += (long long)blockIdx.z * sCz;
  }

  // per-thread ldmatrix lane addressing (80B row stride -> conflict-free)
  const int a_r = ((lane >> 3) & 1) * 8 + (lane & 7);
  const int a_k = (lane >> 4) * 16;
  uint32_t aoff[4];
#pragma unroll
  for (int mt = 0; mt < 4; mt++) aoff[mt] = (wm0 + mt * 16 + a_r) * 80 + a_k;
  const int b_r = ((lane >> 4) & 1) * 8 + (lane & 7);
  const int b_k = ((lane >> 3) & 1) * 16;
  uint32_t boff[2];
#pragma unroll
  for (int g = 0; g < 2; g++) boff[g] = (wn0 + g * 16 + b_r) * 80 + b_k;

  float acc[4][4][4];
#pragma unroll
  for (int i = 0; i < 4; i++)
#pragma unroll
    for (int j = 0; j < 4; j++)
#pragma unroll
      for (int l = 0; l < 4; l++) acc[i][j][l] = 0.f;

  auto issue = [&](int st) {
    const int kt = st * 32;
    const uint32_t db = sbase + (uint32_t)(st & 3) * STG;
#pragma unroll
    for (int i = 0; i < 8; i++) {  // 2048 16B-chunks / 256 threads
      const int idx = tid + i * 256;
      const int plane = idx >> 9, rem = idx & 511, row = rem >> 2, cc = rem & 3;
      const __half* src = (plane == 0)   ? Ah + (long long)(m0 + row) * K + kt
                          : (plane == 1) ? Al + (long long)(m0 + row) * K + kt
                          : (plane == 2) ? Bh + (long long)(n0 + row) * K + kt
                                         : Bl + (long long)(n0 + row) * K + kt;
      CP_ASYNC16(db + (uint32_t)plane * 10240 + (uint32_t)(row * 80 + cc * 16),
                 src + cc * 8);
    }
  };

  const int T = K >> 5;
  issue(0); CP_COMMIT;
  issue(1); CP_COMMIT;
  issue(2); CP_COMMIT;

  for (int t = 0; t < T; ++t) {
    asm volatile("cp.async.wait_group 2;" ::: "memory");
    __syncthreads();
    const uint32_t base = sbase + (uint32_t)(t & 3) * STG;

#pragma unroll
    for (int c = 0; c < 2; c++) {  // two k16 chunks per 32-k stage
      unsigned ah[4][4], al[4][4], bh[2][4], bl[2][4];
#pragma unroll
      for (int mt = 0; mt < 4; mt++) ldsm4(ah[mt], base + aoff[mt] + c * 32);
#pragma unroll
      for (int mt = 0; mt < 4; mt++) ldsm4(al[mt], base + 10240 + aoff[mt] + c * 32);
      ldsm4(bh[0], base + 20480 + boff[0] + c * 32);
      ldsm4(bh[1], base + 20480 + boff[1] + c * 32);
      ldsm4(bl[0], base + 30720 + boff[0] + c * 32);
      ldsm4(bl[1], base + 30720 + boff[1] + c * 32);
      // pass-major order: dependent MMAs on one accumulator are 16 apart
#pragma unroll
      for (int mt = 0; mt < 4; mt++)
#pragma unroll
        for (int nt = 0; nt < 4; nt++)
          mma16(acc[mt][nt], ah[mt], &bh[nt >> 1][(nt & 1) * 2]);
#pragma unroll
      for (int mt = 0; mt < 4; mt++)
#pragma unroll
        for (int nt = 0; nt < 4; nt++)
          mma16(acc[mt][nt], al[mt], &bh[nt >> 1][(nt & 1) * 2]);
#pragma unroll
      for (int mt = 0; mt < 4; mt++)
#pragma unroll
        for (int nt = 0; nt < 4; nt++)
          mma16(acc[mt][nt], ah[mt], &bl[nt >> 1][(nt & 1) * 2]);
    }

    if (t + 3 < T) issue(t + 3);
    CP_COMMIT;  // empty groups in the tail keep wait arithmetic uniform
  }
  asm volatile("cp.async.wait_group 0;" ::: "memory");

  // epilogue with optional fp32 store and optional hi/lo emit
  const long long roff =
      (long long)(m0 / row_div) * row_stride + (long long)(m0 % row_div) * N;
  float* Cb = C ? C + roff : nullptr;
  __half* Chb = EMIT ? Ch + roff : nullptr;
  __half* Clb = EMIT ? Cl + roff : nullptr;
  const int qq = lane >> 2, rr = lane & 3;
#pragma unroll
  for (int mt = 0; mt < 4; mt++) {
    const int r0 = wm0 + mt * 16 + qq;
#pragma unroll
    for (int nt = 0; nt < 4; nt++) {
      const int gc = n0 + wn0 + nt * 8 + rr * 2;
      float bv0 = 0.f, bv1 = 0.f;
      if (bias) {
        bv0 = bias[gc];
        bv1 = bias[gc + 1];
      }
      float2 v0, v1;
      v0.x = acc[mt][nt][0] + bv0;
      v0.y = acc[mt][nt][1] + bv1;
      v1.x = acc[mt][nt][2] + bv0;
      v1.y = acc[mt][nt][3] + bv1;
      if (Cb) {
        *(float2*)(Cb + (long long)r0 * N + gc) = v0;
        *(float2*)(Cb + (long long)(r0 + 8) * N + gc) = v1;
      }
      if (EMIT) {
        unsigned hh, ll;
        split2h(v0.x, v0.y, hh, ll);
        *(unsigned*)(Chb + (long long)r0 * N + gc) = hh;
        *(unsigned*)(Clb + (long long)r0 * N + gc) = ll;
        split2h(v1.x, v1.y, hh, ll);
        *(unsigned*)(Chb + (long long)(r0 + 8) * N + gc) = hh;
        *(unsigned*)(Clb + (long long)(r0 + 8) * N + gc) = ll;
      }
    }
  }
}

// elementwise fp32 -> fp16 hi/lo
__global__ void split_ew(const float* __restrict__ s, __half* __restrict__ h,
                         __half* __restrict__ l) {
  const long long i = (long long)blockIdx.x * blockDim.x + threadIdx.x;
  const float4 v = ((const float4*)s)[i];
  unsigned h0, l0, h1, l1;
  split2h(v.x, v.y, h0, l0);
  split2h(v.z, v.w, h1, l1);
  ((uint2*)h)[i] = make_uint2(h0, h1);
  ((uint2*)l)[i] = make_uint2(l0, l1);
}

// fp32 [R][C] -> fp16 hi/lo transposed [C][R]; batched via z
__global__ void split_tr(const float* __restrict__ src, __half* __restrict__ hT,
                         __half* __restrict__ lT, int R, int C, long long szs,
                         long long szd) {
  __shared__ float t[32][33];
  src += (long long)blockIdx.z * szs;
  hT += (long long)blockIdx.z * szd;
  lT += (long long)blockIdx.z * szd;
  const int c0 = blockIdx.x * 32, r0 = blockIdx.y * 32;
  for (int j = threadIdx.y; j < 32; j += 8)
    t[j][threadIdx.x] = src[(long long)(r0 + j) * C + c0 + threadIdx.x];
  __syncthreads();
  for (int j = threadIdx.y; j < 32; j += 8) {
    const float v = t[threadIdx.x][j];
    const __half h = __float2half_rn(v);
    const __half l = __float2half_rn(v - __half2float(h));
    const long long o = (long long)(c0 + j) * R + r0 + threadIdx.x;
    hT[o] = h;
    lT[o] = l;
  }
}

// k cache: fp32 copy into rows [0,2048) of [4,4096,2048] + hi/lo emit
__global__ void copy_cache_k(const float* __restrict__ src, float* __restrict__ dst,
                             __half* __restrict__ kh, __half* __restrict__ kl) {
  const long long i = (long long)blockIdx.x * blockDim.x + threadIdx.x;
  const long long per_b = 2048LL * 512;
  const int b = (int)(i / per_b);
  const long long rem = i - (long long)b * per_b;
  const long long o = (long long)b * 4096 * 512 + rem;
  const float4 v = ((const float4*)src)[i];
  ((float4*)dst)[o] = v;
  unsigned h0, l0, h1, l1;
  split2h(v.x, v.y, h0, l0);
  split2h(v.z, v.w, h1, l1);
  ((uint2*)kh)[o] = make_uint2(h0, h1);
  ((uint2*)kl)[o] = make_uint2(l0, l1);
}

__global__ void copy_cache(const float* __restrict__ src, float* __restrict__ dst) {
  const long long i = (long long)blockIdx.x * blockDim.x + threadIdx.x;
  const long long per_b = 2048LL * 512;
  const int b = (int)(i / per_b);
  const long long rem = i - (long long)b * per_b;
  ((float4*)dst)[(long long)b * 4096 * 512 + rem] = ((const float4*)src)[i];
}

// softmax over QUERY axis of scores [4,2048,4096]; writes attn as fp16 hi/lo
__global__ void softmax_q_split(const float* __restrict__ s, __half* __restrict__ oh,
                                __half* __restrict__ ol) {
  const int col = blockIdx.x * blockDim.x + threadIdx.x;
  const long long base = (long long)blockIdx.y * 2048 * 4096 + col;
  const float* p = s + base;
  float mx = -1e30f;
#pragma unroll 16
  for (int i = 0; i < 2048; i++) mx = fmaxf(mx, p[(long long)i * 4096]);
  float sum = 0.f;
#pragma unroll 16
  for (int i = 0; i < 2048; i++) sum += __expf(p[(long long)i * 4096] - mx);
  const float inv = 1.f / sum;
#pragma unroll 16
  for (int i = 0; i < 2048; i++) {
    const float a = __expf(p[(long long)i * 4096] - mx) * inv;
    const long long o = base + (long long)i * 4096;
    const __half h = __float2half_rn(a);
    oh[o] = h;
    ol[o] = __float2half_rn(a - __half2float(h));
  }
}

extern "C" void kernel_launch(void* const* d_in, const int* in_sizes, int n_in,
                              void* d_out, int out_size) {
  const float* x = (const float*)d_in[0];
  const float* k_cache = (const float*)d_in[1];
  const float* v_cache = (const float*)d_in[2];
  const float* Wq = (const float*)d_in[3];
  const float* bq = (const float*)d_in[4];
  const float* Wk = (const float*)d_in[5];
  const float* bk = (const float*)d_in[6];
  const float* Wv = (const float*)d_in[7];
  const float* bv = (const float*)d_in[8];
  const float* Wff = (const float*)d_in[9];
  const float* bff = (const float*)d_in[10];
  const float* Wout = (const float*)d_in[11];
  const float* bout = (const float*)d_in[12];

  float* out = (float*)d_out;            // [4,2048,2048]
  float* k_out = out + 16777216LL;       // [4,4096,2048]
  float* v_out = k_out + 33554432LL;     // [4,4096,2048]

  float* sc;
  cudaGetSymbolAddress((void**)&sc, g_scores);
#define SYM(var, sym) __half* var; cudaGetSymbolAddress((void**)&var, sym)
  SYM(xh, g_xh);   SYM(xl, g_xl);
  SYM(wqh, g_wqh); SYM(wql, g_wql);
  SYM(wkh, g_wkh); SYM(wkl, g_wkl);
  SYM(wvh, g_wvh); SYM(wvl, g_wvl);
  SYM(wfh, g_wfh); SYM(wfl, g_wfl);
  SYM(woh, g_woh); SYM(wol, g_wol);
  SYM(qh, g_qh);   SYM(ql, g_ql);
  SYM(kh, g_kh);   SYM(kl, g_kl);
  SYM(vth, g_vth); SYM(vtl, g_vtl);
  SYM(sh, g_sh);   SYM(sl, g_sl);
  SYM(ch, g_ch);   SYM(cl, g_cl);
  SYM(fh, g_fh);   SYM(fl, g_fl);
#undef SYM

  const int SMEM = 4 * 40960;  // 163840
  cudaFuncSetAttribute(gemm_h<false>, cudaFuncAttributeMaxDynamicSharedMemorySize, SMEM);
  cudaFuncSetAttribute(gemm_h<true>, cudaFuncAttributeMaxDynamicSharedMemorySize, SMEM);

  const dim3 blk(256);
  const dim3 t32(32, 8);

  // cache copies (k emits hi/lo) + input/weight splits
  copy_cache_k<<<16384, 256>>>(k_cache, k_out, kh, kl);
  copy_cache<<<16384, 256>>>(v_cache, v_out);
  split_ew<<<16384, 256>>>(x, xh, xl);
  split_tr<<<dim3(64, 64, 1), t32>>>(Wq, wqh, wql, 2048, 2048, 0, 0);
  split_tr<<<dim3(64, 64, 1), t32>>>(Wk, wkh, wkl, 2048, 2048, 0, 0);
  split_tr<<<dim3(64, 64, 1), t32>>>(Wv, wvh, wvl, 2048, 2048, 0, 0);
  split_tr<<<dim3(256, 64, 1), t32>>>(Wff, wfh, wfl, 2048, 8192, 0, 0);
  split_tr<<<dim3(64, 256, 1), t32>>>(Wout, woh, wol, 8192, 2048, 0, 0);

  // q-proj: emit split only
  gemm_h<true><<<dim3(16, 64, 1), blk, SMEM>>>(
      xh, xl, wqh, wql, bq, nullptr, qh, ql,
      8192, 2048, 2048, 0, 0, 0, 8192, 0);
  // k-proj: fp32 into cache rows [2048,4096) + split emit (same remap)
  gemm_h<true><<<dim3(16, 64, 1), blk, SMEM>>>(
      xh, xl, wkh, wkl, bk, k_out + 2048LL * 2048, kh + 2048LL * 2048,
      kl + 2048LL * 2048, 8192, 2048, 2048, 0, 0, 0, 2048, 4096LL * 2048);
  // v-proj: fp32 only (split comes from the V^T pass)
  gemm_h<false><<<dim3(16, 64, 1), blk, SMEM>>>(
      xh, xl, wvh, wvl, bv, v_out + 2048LL * 2048, nullptr, nullptr,
      8192, 2048, 2048, 0, 0, 0, 2048, 4096LL * 2048);

  // V^T split per batch: [4096,2048] -> [2048,4096]
  split_tr<<<dim3(64, 128, 4), t32>>>(v_out, vth, vtl, 4096, 2048,
                                      4096LL * 2048, 2048LL * 4096);

  // scores = q @ k^T
  gemm_h<false><<<dim3(32, 16, 4), blk, SMEM>>>(
      qh, ql, kh, kl, nullptr, sc, nullptr, nullptr,
      2048, 4096, 2048, 2048LL * 2048, 4096LL * 2048, 2048LL * 4096, 2048, 0);

  softmax_q_split<<<dim3(16, 4), 256>>>(sc, sh, sl);

  // ctx = attn @ V (B = V^T planes), emit split only
  gemm_h<true><<<dim3(16, 16, 4), blk, SMEM>>>(
      sh, sl, vth, vtl, nullptr, nullptr, ch, cl,
      2048, 2048, 4096, 2048LL * 4096, 2048LL * 4096, 2048LL * 2048, 2048, 0);

  // FFN
  gemm_h<true><<<dim3(64, 64, 1), blk, SMEM>>>(
      ch, cl, wfh, wfl, bff, nullptr, fh, fl,
      8192, 8192, 2048, 0, 0, 0, 8192, 0);
  gemm_h<false><<<dim3(16, 64, 1), blk, SMEM>>>(
      fh, fl, woh, wol, bout, out, nullptr, nullptr,
      8192, 2048, 8192, 0, 0, 0, 8192, 0);
}